// round 4
// baseline (speedup 1.0000x reference)
#include <cuda_runtime.h>

#define NB 32
#define NP 256
#define ND 64
#define NT 4096
#define TCHUNK 256
#define NCHUNK 16   // NT / TCHUNK

#define LOGNORM (-0.9189385332046727f)   // -log(1.0) - 0.5*log(2*pi)

// Partials per (b, p, chunk): x = chunk max (shift), y = sum(exp), z = sum(exp*pred)
__device__ float4 g_part[NB * NP * NCHUNK];

// exp(x) for x <= 0 on the FMA pipe (MUFU at 33.5M exps would bottleneck).
// 2^f Taylor deg-6 on [0,1): rel err ~1.6e-5. Clamped, underflow-safe.
// NOTE: only harmless now — the shift is the *current* max, so the leading
// task always evaluates exp(0)=1 and clamped tails are negligible.
__device__ __forceinline__ float fast_exp_neg(float x) {
    float y = x * 1.4426950408889634f;
    y = fmaxf(y, -126.0f);
    float fl = floorf(y);
    float f  = y - fl;
    float pz = 1.5403530393381608e-4f;
    pz = fmaf(pz, f, 1.3333558146428443e-3f);
    pz = fmaf(pz, f, 9.618129107628477e-3f);
    pz = fmaf(pz, f, 5.550410866482158e-2f);
    pz = fmaf(pz, f, 2.402265069591007e-1f);
    pz = fmaf(pz, f, 6.931471805599453e-1f);
    pz = fmaf(pz, f, 1.0f);
    return pz * __int_as_float(((int)fl + 127) << 23);
}

// ------------------------------------------------------------------
// CTA = (t-chunk, b). One task per thread. Sequential over p carrying
// the exclusive prefix cumsum c (Kahan). Per p: block-reduce the
// CURRENT max, then exp against it, then block-reduce (S, V).
// ------------------------------------------------------------------
__global__ void __launch_bounds__(256)
mmse_main(const float* __restrict__ data,
          const float* __restrict__ targets,
          const float* __restrict__ task_pool)
{
    const int chunk = blockIdx.x;
    const int b     = blockIdx.y;
    const int tid   = threadIdx.x;
    const int lane  = tid & 31;
    const int warp  = tid >> 5;
    const int t     = chunk * TCHUNK + tid;

    __shared__ float stgt[NP];
    __shared__ float sM[8], sS[8], sV[8];

    // W column (64 contiguous floats) in registers
    float w[ND];
    {
        const float4* wp = (const float4*)(task_pool + (size_t)t * ND);
        #pragma unroll
        for (int i = 0; i < 16; ++i) {
            float4 q = __ldg(wp + i);
            w[4 * i + 0] = q.x;
            w[4 * i + 1] = q.y;
            w[4 * i + 2] = q.z;
            w[4 * i + 3] = q.w;
        }
    }
    stgt[tid] = targets[b * NP + tid];
    __syncthreads();

    const float4* drow = (const float4*)(data + (size_t)b * NP * ND);

    float c    = 0.0f;   // exclusive prefix cumsum of scores (Kahan)
    float comp = 0.0f;

    #pragma unroll 1
    for (int p = 0; p < NP; ++p) {
        const float4* row = drow + p * 16;

        // dot = data[b,p,:] . W[:,t]  (4 independent FMA chains)
        float d0 = 0.f, d1 = 0.f, d2 = 0.f, d3 = 0.f;
        #pragma unroll
        for (int i = 0; i < 16; ++i) {
            float4 v = __ldg(row + i);   // uniform address across warp -> 1 sector
            d0 = fmaf(v.x, w[4 * i + 0], d0);
            d1 = fmaf(v.y, w[4 * i + 1], d1);
            d2 = fmaf(v.z, w[4 * i + 2], d2);
            d3 = fmaf(v.w, w[4 * i + 3], d3);
        }
        const float dot  = (d0 + d1) + (d2 + d3);
        const float llik = c;                 // posterior logit for point p

        // score = -0.5*err^2 + log_norm; Kahan-accumulate into c
        const float err = stgt[p] - dot;
        const float sc  = __fadd_rn(__fmul_rn(-0.5f, __fmul_rn(err, err)), LOGNORM);
        {
            float y  = sc - comp;
            float tt = c + y;
            comp = (tt - c) - y;
            c = tt;
        }

        // ---- Phase 1: current chunk max of llik ----
        float m = llik;
        #pragma unroll
        for (int off = 16; off > 0; off >>= 1)
            m = fmaxf(m, __shfl_xor_sync(0xffffffffu, m, off));
        if (lane == 0) sM[warp] = m;
        __syncthreads();

        const float mAll =
            fmaxf(fmaxf(fmaxf(sM[0], sM[1]), fmaxf(sM[2], sM[3])),
                  fmaxf(fmaxf(sM[4], sM[5]), fmaxf(sM[6], sM[7])));

        // ---- Phase 2: exp against the CURRENT max (leader -> exp(0)=1) ----
        const float e = fast_exp_neg(llik - mAll);
        float S = e;
        float V = e * dot;
        #pragma unroll
        for (int off = 16; off > 0; off >>= 1) {
            S += __shfl_xor_sync(0xffffffffu, S, off);
            V += __shfl_xor_sync(0xffffffffu, V, off);
        }
        if (lane == 0) { sS[warp] = S; sV[warp] = V; }
        __syncthreads();

        if (tid == 0) {
            float St = ((sS[0] + sS[1]) + (sS[2] + sS[3]))
                     + ((sS[4] + sS[5]) + (sS[6] + sS[7]));
            float Vt = ((sV[0] + sV[1]) + (sV[2] + sV[3]))
                     + ((sV[4] + sV[5]) + (sV[6] + sV[7]));
            g_part[((size_t)b * NP + p) * NCHUNK + chunk] =
                make_float4(mAll, St, Vt, 0.0f);
        }
        // sM is re-written only after the NEXT iteration's first barrier,
        // and tid0's sS/sV reads finish before it reaches that barrier.
    }
}

// ------------------------------------------------------------------
// Combine: per (b,p), log-sum-exp merge of the 16 chunk partials.
// out = sum_i exp(M_i - M*) V_i / sum_i exp(M_i - M*) S_i
// ------------------------------------------------------------------
__global__ void mmse_combine(float* __restrict__ out)
{
    const int idx = blockIdx.x * blockDim.x + threadIdx.x;   // b*NP + p
    const float4* pp = g_part + (size_t)idx * NCHUNK;

    float4 loc[NCHUNK];
    float Mx = -3.4e38f;
    #pragma unroll
    for (int i = 0; i < NCHUNK; ++i) {
        loc[i] = pp[i];
        Mx = fmaxf(Mx, loc[i].x);
    }
    float S = 0.0f, V = 0.0f;
    #pragma unroll
    for (int i = 0; i < NCHUNK; ++i) {
        float e = fast_exp_neg(loc[i].x - Mx);
        S = fmaf(e, loc[i].y, S);
        V = fmaf(e, loc[i].z, V);
    }
    out[idx] = V / S;
}

// ------------------------------------------------------------------
extern "C" void kernel_launch(void* const* d_in, const int* in_sizes, int n_in,
                              void* d_out, int out_size)
{
    (void)out_size;
    // Map inputs by element count (defensive): data=524288, targets=8192,
    // task_pool=262144.
    const float* data      = (const float*)d_in[0];
    const float* targets   = (const float*)d_in[1];
    const float* task_pool = (const float*)d_in[2];
    for (int i = 0; i < n_in; ++i) {
        if (in_sizes[i] == NB * NP * ND)      data      = (const float*)d_in[i];
        else if (in_sizes[i] == NB * NP)      targets   = (const float*)d_in[i];
        else if (in_sizes[i] == NT * ND)      task_pool = (const float*)d_in[i];
    }
    float* out = (float*)d_out;   // (B, P)

    dim3 grid(NCHUNK, NB);
    mmse_main<<<grid, 256>>>(data, targets, task_pool);
    mmse_combine<<<(NB * NP) / 256, 256>>>(out);
}

// round 6
// speedup vs baseline: 1.1733x; 1.1733x over previous
#include <cuda_runtime.h>

#define NB 32
#define NP 256
#define ND 64
#define NT 4096
#define TCHUNK 256
#define NCHUNK 16   // NT / TCHUNK
#define NWARP 8     // warps per CTA
#define NPART (NCHUNK * NWARP)   // 128 per-warp partials per (b,p)

#define LOGNORM (-0.9189385332046727f)   // -log(1.0) - 0.5*log(2*pi)

typedef unsigned long long u64;

// Per-warp partials: (warp max m, sum exp S, sum exp*pred V, pad)
// layout: ((b*NP + p) * NCHUNK + chunk) * NWARP + warp
__device__ float4 g_part[NB * NP * NPART];

// ---------- packed f32x2 helpers (bit-equivalent to two scalar FMAs) ----------
__device__ __forceinline__ u64 fma2(u64 a, u64 b, u64 acc) {
    u64 r;
    asm("fma.rn.f32x2 %0, %1, %2, %3;" : "=l"(r) : "l"(a), "l"(b), "l"(acc));
    return r;
}
__device__ __forceinline__ u64 add2(u64 a, u64 b) {
    u64 r;
    asm("add.rn.f32x2 %0, %1, %2;" : "=l"(r) : "l"(a), "l"(b));
    return r;
}
__device__ __forceinline__ float2 u2f(u64 a) {
    float2 r;
    asm("mov.b64 {%0, %1}, %2;" : "=f"(r.x), "=f"(r.y) : "l"(a));
    return r;
}

// exp(x) for x <= 0 on the FMA pipe (33.5M exps would wall on MUFU rt=8).
// 2^f Taylor deg-6 on [0,1): rel err ~1.6e-5. Clamp only trims negligible tails
// (the warp leader always evaluates exp(0)=1).
__device__ __forceinline__ float fast_exp_neg(float x) {
    float y = x * 1.4426950408889634f;
    y = fmaxf(y, -126.0f);
    float fl = floorf(y);
    float f  = y - fl;
    float pz = 1.5403530393381608e-4f;
    pz = fmaf(pz, f, 1.3333558146428443e-3f);
    pz = fmaf(pz, f, 9.618129107628477e-3f);
    pz = fmaf(pz, f, 5.550410866482158e-2f);
    pz = fmaf(pz, f, 2.402265069591007e-1f);
    pz = fmaf(pz, f, 6.931471805599453e-1f);
    pz = fmaf(pz, f, 1.0f);
    return pz * __int_as_float(((int)fl + 127) << 23);
}

// ------------------------------------------------------------------
// CTA = (t-chunk, b). One task per thread. NO barriers in the p loop:
// each warp emits its own exact-max softmax partial per p.
// ------------------------------------------------------------------
__global__ void __launch_bounds__(256, 2)
mmse_main(const float* __restrict__ data,
          const float* __restrict__ targets,
          const float* __restrict__ task_pool)
{
    const int chunk = blockIdx.x;
    const int b     = blockIdx.y;
    const int tid   = threadIdx.x;
    const int lane  = tid & 31;
    const int warp  = tid >> 5;
    const int t     = chunk * TCHUNK + tid;

    __shared__ float stgt[NP];

    // W column (64 contiguous floats) as 32 packed f32x2 registers
    u64 w2[32];
    {
        const ulonglong2* wp = (const ulonglong2*)(task_pool + (size_t)t * ND);
        #pragma unroll
        for (int i = 0; i < 16; ++i) {
            ulonglong2 q = __ldg(wp + i);
            w2[2 * i]     = q.x;
            w2[2 * i + 1] = q.y;
        }
    }
    stgt[tid] = targets[b * NP + tid];
    __syncthreads();   // only barrier in the kernel (stgt init)

    const ulonglong2* drow = (const ulonglong2*)(data + (size_t)b * NP * ND);
    float4* mypart = g_part + ((size_t)b * NP * NCHUNK + chunk) * NWARP + warp;

    float c    = 0.0f;   // exclusive prefix cumsum of scores (Kahan)
    float comp = 0.0f;

    #pragma unroll 1
    for (int p = 0; p < NP; ++p) {
        // row = 64 floats = 16 ulonglong2  (256 B per row)
        const ulonglong2* row = drow + p * 16;

        // dot = data[b,p,:] . W[:,t]  (packed f32x2, 4 independent chains)
        // float-pair k of the row multiplies w2[k]; i covers {0,2,...,14}.
        u64 a0 = 0ull, a1 = 0ull, a2 = 0ull, a3 = 0ull;
        #pragma unroll
        for (int i = 0; i < 16; i += 2) {
            ulonglong2 x = __ldg(row + i);       // uniform across warp -> 1 sector
            ulonglong2 y = __ldg(row + i + 1);
            a0 = fma2(x.x, w2[2 * i],     a0);
            a1 = fma2(x.y, w2[2 * i + 1], a1);
            a2 = fma2(y.x, w2[2 * i + 2], a2);
            a3 = fma2(y.y, w2[2 * i + 3], a3);
        }
        a0 = add2(a0, a1);
        a2 = add2(a2, a3);
        a0 = add2(a0, a2);
        const float2 dv  = u2f(a0);
        const float  dot = dv.x + dv.y;
        const float  llik = c;                // posterior logit for point p

        // score = -0.5*err^2 + log_norm; Kahan-accumulate into c
        const float err = stgt[p] - dot;
        const float sc  = __fadd_rn(__fmul_rn(-0.5f, __fmul_rn(err, err)), LOGNORM);
        {
            float y  = sc - comp;
            float tt = c + y;
            comp = (tt - c) - y;
            c = tt;
        }

        // ---- exact warp max, then exp against it (leader -> exp(0)=1) ----
        float m = llik;
        #pragma unroll
        for (int off = 16; off > 0; off >>= 1)
            m = fmaxf(m, __shfl_xor_sync(0xffffffffu, m, off));

        const float e = fast_exp_neg(llik - m);
        float S = e;
        float V = e * dot;
        #pragma unroll
        for (int off = 16; off > 0; off >>= 1) {
            S += __shfl_xor_sync(0xffffffffu, S, off);
            V += __shfl_xor_sync(0xffffffffu, V, off);
        }

        if (lane == 0)
            mypart[(size_t)p * NPART] = make_float4(m, S, V, 0.0f);
    }
}

// ------------------------------------------------------------------
// Combine: one warp per (b,p); LSE-merge its 128 per-warp partials.
// ------------------------------------------------------------------
__global__ void __launch_bounds__(256)
mmse_combine(float* __restrict__ out)
{
    const int warp = threadIdx.x >> 5;
    const int lane = threadIdx.x & 31;
    const int idx  = blockIdx.x * 8 + warp;    // b*NP + p
    const float4* pp = g_part + (size_t)idx * NPART + lane * 4;

    float4 l0 = pp[0], l1 = pp[1], l2 = pp[2], l3 = pp[3];

    float m = fmaxf(fmaxf(l0.x, l1.x), fmaxf(l2.x, l3.x));
    #pragma unroll
    for (int off = 16; off > 0; off >>= 1)
        m = fmaxf(m, __shfl_xor_sync(0xffffffffu, m, off));

    float e0 = fast_exp_neg(l0.x - m);
    float e1 = fast_exp_neg(l1.x - m);
    float e2 = fast_exp_neg(l2.x - m);
    float e3 = fast_exp_neg(l3.x - m);
    float S = fmaf(e0, l0.y, fmaf(e1, l1.y, fmaf(e2, l2.y, e3 * l3.y)));
    float V = fmaf(e0, l0.z, fmaf(e1, l1.z, fmaf(e2, l2.z, e3 * l3.z)));
    #pragma unroll
    for (int off = 16; off > 0; off >>= 1) {
        S += __shfl_xor_sync(0xffffffffu, S, off);
        V += __shfl_xor_sync(0xffffffffu, V, off);
    }

    if (lane == 0) out[idx] = V / S;
}

// ------------------------------------------------------------------
extern "C" void kernel_launch(void* const* d_in, const int* in_sizes, int n_in,
                              void* d_out, int out_size)
{
    (void)out_size;
    const float* data      = (const float*)d_in[0];
    const float* targets   = (const float*)d_in[1];
    const float* task_pool = (const float*)d_in[2];
    for (int i = 0; i < n_in; ++i) {
        if (in_sizes[i] == NB * NP * ND)      data      = (const float*)d_in[i];
        else if (in_sizes[i] == NB * NP)      targets   = (const float*)d_in[i];
        else if (in_sizes[i] == NT * ND)      task_pool = (const float*)d_in[i];
    }
    float* out = (float*)d_out;   // (B, P)

    dim3 grid(NCHUNK, NB);
    mmse_main<<<grid, 256>>>(data, targets, task_pool);
    mmse_combine<<<(NB * NP) / 8, 256>>>(out);
}

// round 7
// speedup vs baseline: 1.9756x; 1.6839x over previous
#include <cuda_runtime.h>

#define NB 32
#define NP 256
#define ND 64
#define NT 4096
#define TCHUNK 256
#define NCHUNK 16   // NT / TCHUNK
#define NWARP 8     // warps per CTA
#define NPART (NCHUNK * NWARP)   // 128 per-warp partials per (b,p)
#define PTILE 16    // p rows staged per smem tile

#define LOGNORM (-0.9189385332046727f)   // -log(1.0) - 0.5*log(2*pi)

typedef unsigned long long u64;

// Per-warp partials: (warp max m, sum exp S, sum exp*pred V, pad)
__device__ float4 g_part[NB * NP * NPART];
__device__ int g_sink;   // keeps nop kernels from being empty

// ---------- packed f32x2 helpers (bit-equivalent to two scalar FMAs) ----------
__device__ __forceinline__ u64 fma2(u64 a, u64 b, u64 acc) {
    u64 r;
    asm("fma.rn.f32x2 %0, %1, %2, %3;" : "=l"(r) : "l"(a), "l"(b), "l"(acc));
    return r;
}
__device__ __forceinline__ u64 add2(u64 a, u64 b) {
    u64 r;
    asm("add.rn.f32x2 %0, %1, %2;" : "=l"(r) : "l"(a), "l"(b));
    return r;
}
__device__ __forceinline__ float2 u2f(u64 a) {
    float2 r;
    asm("mov.b64 {%0, %1}, %2;" : "=f"(r.x), "=f"(r.y) : "l"(a));
    return r;
}

// exp(x) for x <= 0 on the FMA pipe. 2^f Taylor deg-6: rel err ~1.6e-5.
// Clamp only trims negligible tails (warp leader always evaluates exp(0)=1).
__device__ __forceinline__ float fast_exp_neg(float x) {
    float y = x * 1.4426950408889634f;
    y = fmaxf(y, -126.0f);
    float fl = floorf(y);
    float f  = y - fl;
    float pz = 1.5403530393381608e-4f;
    pz = fmaf(pz, f, 1.3333558146428443e-3f);
    pz = fmaf(pz, f, 9.618129107628477e-3f);
    pz = fmaf(pz, f, 5.550410866482158e-2f);
    pz = fmaf(pz, f, 2.402265069591007e-1f);
    pz = fmaf(pz, f, 6.931471805599453e-1f);
    pz = fmaf(pz, f, 1.0f);
    return pz * __int_as_float(((int)fl + 127) << 23);
}

// Profiling pad: keeps ncu's fixed "-s 5" aligned onto mmse_main (4 launches
// per kernel_launch call; 5 mod 4 == 1 == mmse_main's slot).
__global__ void mmse_nop(int phase) {
    if ((int)threadIdx.x == 47) g_sink = phase;   // blockDim=32: never taken
}

// ------------------------------------------------------------------
// CTA = (t-chunk, b). One task per thread. Data rows staged through a
// double-buffered smem tile (1 LDG.128/thread per 16 p). No barriers
// except 1 per 16-p tile. Per-warp softmax partials -> global.
// ------------------------------------------------------------------
__global__ void __launch_bounds__(256, 2)
mmse_main(const float* __restrict__ data,
          const float* __restrict__ targets,
          const float* __restrict__ task_pool)
{
    const int chunk = blockIdx.x;
    const int b     = blockIdx.y;
    const int tid   = threadIdx.x;
    const int lane  = tid & 31;
    const int warp  = tid >> 5;
    const int t     = chunk * TCHUNK + tid;

    __shared__ float stgt[NP];
    __shared__ float srow[2][PTILE][ND];   // 2 x 4KB row tiles

    // W column (64 contiguous floats) as 32 packed f32x2 registers
    u64 w2[32];
    {
        const ulonglong2* wp = (const ulonglong2*)(task_pool + (size_t)t * ND);
        #pragma unroll
        for (int i = 0; i < 16; ++i) {
            ulonglong2 q = __ldg(wp + i);
            w2[2 * i]     = q.x;
            w2[2 * i + 1] = q.y;
        }
    }
    stgt[tid] = targets[b * NP + tid];

    // data slab for this b, as float4: tile T = float4 [256*T, 256*(T+1))
    const float4* dbase4 = (const float4*)(data + (size_t)b * NP * ND);

    // preload tile 0 (256 float4 == 256 threads: one each)
    ((float4*)srow[0])[tid] = __ldg(dbase4 + tid);
    __syncthreads();

    float4* mypart = g_part + ((size_t)b * NP * NCHUNK + chunk) * NWARP + warp;
    float c = 0.0f;   // exclusive prefix cumsum of scores

    #pragma unroll 1
    for (int tile = 0; tile < NP / PTILE; ++tile) {
        const int buf = tile & 1;

        // prefetch next tile into the other buffer (issued ~16 p's ahead)
        if (tile + 1 < NP / PTILE)
            ((float4*)srow[buf ^ 1])[tid] = __ldg(dbase4 + (tile + 1) * 256 + tid);

        #pragma unroll 1
        for (int pp = 0; pp < PTILE; ++pp) {
            const int p = tile * PTILE + pp;
            const ulonglong2* row = (const ulonglong2*)srow[buf][pp];

            // dot = data[b,p,:] . W[:,t]  (packed f32x2, 4 chains; LDS broadcast)
            u64 a0 = 0ull, a1 = 0ull, a2 = 0ull, a3 = 0ull;
            #pragma unroll
            for (int i = 0; i < 16; i += 2) {
                ulonglong2 x = row[i];
                ulonglong2 y = row[i + 1];
                a0 = fma2(x.x, w2[2 * i],     a0);
                a1 = fma2(x.y, w2[2 * i + 1], a1);
                a2 = fma2(y.x, w2[2 * i + 2], a2);
                a3 = fma2(y.y, w2[2 * i + 3], a3);
            }
            a0 = add2(a0, a1);
            a2 = add2(a2, a3);
            a0 = add2(a0, a2);
            const float2 dv   = u2f(a0);
            const float  dot  = dv.x + dv.y;
            const float  llik = c;                // posterior logit for point p

            // score = -0.5*err^2 + log_norm (reference op order)
            const float err = stgt[p] - dot;
            c = __fadd_rn(c, __fadd_rn(__fmul_rn(-0.5f, __fmul_rn(err, err)),
                                       LOGNORM));

            // exact warp max, then exp against it (leader -> exp(0)=1)
            float m = llik;
            #pragma unroll
            for (int off = 16; off > 0; off >>= 1)
                m = fmaxf(m, __shfl_xor_sync(0xffffffffu, m, off));

            const float e = fast_exp_neg(llik - m);
            float S = e;
            float V = e * dot;
            #pragma unroll
            for (int off = 16; off > 0; off >>= 1) {
                S += __shfl_xor_sync(0xffffffffu, S, off);
                V += __shfl_xor_sync(0xffffffffu, V, off);
            }

            if (lane == 0)
                mypart[(size_t)p * NPART] = make_float4(m, S, V, 0.0f);
        }
        __syncthreads();   // tile consumed; prefetch writes visible
    }
}

// ------------------------------------------------------------------
// Combine: one warp per (b,p); LSE-merge its 128 per-warp partials.
// ------------------------------------------------------------------
__global__ void __launch_bounds__(256)
mmse_combine(float* __restrict__ out)
{
    const int warp = threadIdx.x >> 5;
    const int lane = threadIdx.x & 31;
    const int idx  = blockIdx.x * 8 + warp;    // b*NP + p
    const float4* pp = g_part + (size_t)idx * NPART + lane * 4;

    float4 l0 = pp[0], l1 = pp[1], l2 = pp[2], l3 = pp[3];

    float m = fmaxf(fmaxf(l0.x, l1.x), fmaxf(l2.x, l3.x));
    #pragma unroll
    for (int off = 16; off > 0; off >>= 1)
        m = fmaxf(m, __shfl_xor_sync(0xffffffffu, m, off));

    float e0 = fast_exp_neg(l0.x - m);
    float e1 = fast_exp_neg(l1.x - m);
    float e2 = fast_exp_neg(l2.x - m);
    float e3 = fast_exp_neg(l3.x - m);
    float S = fmaf(e0, l0.y, fmaf(e1, l1.y, fmaf(e2, l2.y, e3 * l3.y)));
    float V = fmaf(e0, l0.z, fmaf(e1, l1.z, fmaf(e2, l2.z, e3 * l3.z)));
    #pragma unroll
    for (int off = 16; off > 0; off >>= 1) {
        S += __shfl_xor_sync(0xffffffffu, S, off);
        V += __shfl_xor_sync(0xffffffffu, V, off);
    }

    if (lane == 0) out[idx] = V / S;
}

// ------------------------------------------------------------------
extern "C" void kernel_launch(void* const* d_in, const int* in_sizes, int n_in,
                              void* d_out, int out_size)
{
    (void)out_size;
    const float* data      = (const float*)d_in[0];
    const float* targets   = (const float*)d_in[1];
    const float* task_pool = (const float*)d_in[2];
    for (int i = 0; i < n_in; ++i) {
        if (in_sizes[i] == NB * NP * ND)      data      = (const float*)d_in[i];
        else if (in_sizes[i] == NB * NP)      targets   = (const float*)d_in[i];
        else if (in_sizes[i] == NT * ND)      task_pool = (const float*)d_in[i];
    }
    float* out = (float*)d_out;   // (B, P)

    // 4 launches per call: ncu -s 5 (5 mod 4 == 1) lands on mmse_main.
    mmse_nop<<<1, 32>>>(0);
    dim3 grid(NCHUNK, NB);
    mmse_main<<<grid, 256>>>(data, targets, task_pool);
    mmse_combine<<<(NB * NP) / 8, 256>>>(out);
    mmse_nop<<<1, 32>>>(1);
}

// round 9
// speedup vs baseline: 2.3726x; 1.2009x over previous
#include <cuda_runtime.h>

#define NB 32
#define NP 256
#define ND 64
#define NT 4096
#define TCHUNK 256
#define NCHUNK 16   // NT / TCHUNK
#define NWARP 8     // warps per CTA
#define NPART (NCHUNK * NWARP)   // 128 per-warp partials per (b,p)
#define PTILE 16    // p rows staged per smem tile

#define LOGNORM (-0.9189385332046727f)   // -log(1.0) - 0.5*log(2*pi)
#define LOG2E   (1.4426950408889634f)

typedef unsigned long long u64;

// Per-warp partials: (warp max m, sum exp S, sum exp*pred V, pad)
__device__ float4 g_part[NB * NP * NPART];

// ---------- packed f32x2 helpers (bit-equivalent to two scalar FMAs) ----------
__device__ __forceinline__ u64 fma2(u64 a, u64 b, u64 acc) {
    u64 r;
    asm("fma.rn.f32x2 %0, %1, %2, %3;" : "=l"(r) : "l"(a), "l"(b), "l"(acc));
    return r;
}
__device__ __forceinline__ u64 add2(u64 a, u64 b) {
    u64 r;
    asm("add.rn.f32x2 %0, %1, %2;" : "=l"(r) : "l"(a), "l"(b));
    return r;
}
__device__ __forceinline__ float2 u2f(u64 a) {
    float2 r;
    asm("mov.b64 {%0, %1}, %2;" : "=f"(r.x), "=f"(r.y) : "l"(a));
    return r;
}

// Warp float-max for values <= 0 in ONE instruction:
// non-positive floats (with +0.0 -> bits 0x00000000) order inversely to their
// unsigned bit patterns, so float-max == u32-min over raw bits. redux.sync
// integer ops are sm_80+, legal on sm_103a.
__device__ __forceinline__ float warp_max_nonpos(float x) {
    return __uint_as_float(__reduce_min_sync(0xffffffffu, __float_as_uint(x)));
}

// exp via MUFU: 2^(x*log2e). Arg <= 0; large-negative flushes toward 0
// (harmless: the warp leader always evaluates ex2(0)=1 exactly).
__device__ __forceinline__ float mufu_exp(float x) {
    float r;
    asm("ex2.approx.f32 %0, %1;" : "=f"(r) : "f"(x * LOG2E));
    return r;
}

// ------------------------------------------------------------------
// CTA = (t-chunk, b). One task per thread. Data rows double-buffered
// through smem (1 LDG.128/thread per 16 p). Two p's per inner step:
// their reduction chains interleave, halving exposed SHFL latency.
// ------------------------------------------------------------------
__global__ void __launch_bounds__(256, 2)
mmse_main(const float* __restrict__ data,
          const float* __restrict__ targets,
          const float* __restrict__ task_pool)
{
    const int chunk = blockIdx.x;
    const int b     = blockIdx.y;
    const int tid   = threadIdx.x;
    const int lane  = tid & 31;
    const int warp  = tid >> 5;
    const int t     = chunk * TCHUNK + tid;

    __shared__ float stgt[NP];
    __shared__ float srow[2][PTILE][ND];   // 2 x 4KB row tiles

    // W column (64 contiguous floats) as 32 packed f32x2 registers
    u64 w2[32];
    {
        const ulonglong2* wp = (const ulonglong2*)(task_pool + (size_t)t * ND);
        #pragma unroll
        for (int i = 0; i < 16; ++i) {
            ulonglong2 q = __ldg(wp + i);
            w2[2 * i]     = q.x;
            w2[2 * i + 1] = q.y;
        }
    }
    stgt[tid] = targets[b * NP + tid];

    const float4* dbase4 = (const float4*)(data + (size_t)b * NP * ND);
    ((float4*)srow[0])[tid] = __ldg(dbase4 + tid);   // preload tile 0
    __syncthreads();

    float4* mypart = g_part + ((size_t)b * NP * NCHUNK + chunk) * NWARP + warp;
    float c = 0.0f;   // exclusive prefix cumsum of scores (<= 0 always)

    #pragma unroll 1
    for (int tile = 0; tile < NP / PTILE; ++tile) {
        const int buf = tile & 1;

        if (tile + 1 < NP / PTILE)   // prefetch next tile (~16 p's ahead)
            ((float4*)srow[buf ^ 1])[tid] = __ldg(dbase4 + (tile + 1) * 256 + tid);

        #pragma unroll 1
        for (int pp = 0; pp < PTILE; pp += 2) {
            const int p0 = tile * PTILE + pp;

            // ---- two dots from smem (broadcast LDS, packed FMA2) ----
            float dot[2];
            #pragma unroll
            for (int k = 0; k < 2; ++k) {
                const ulonglong2* row = (const ulonglong2*)srow[buf][pp + k];
                u64 a0 = 0ull, a1 = 0ull, a2 = 0ull, a3 = 0ull;
                #pragma unroll
                for (int i = 0; i < 16; i += 2) {
                    ulonglong2 x = row[i];
                    ulonglong2 y = row[i + 1];
                    a0 = fma2(x.x, w2[2 * i],     a0);
                    a1 = fma2(x.y, w2[2 * i + 1], a1);
                    a2 = fma2(y.x, w2[2 * i + 2], a2);
                    a3 = fma2(y.y, w2[2 * i + 3], a3);
                }
                a0 = add2(a0, a1);
                a2 = add2(a2, a3);
                a0 = add2(a0, a2);
                const float2 dv = u2f(a0);
                dot[k] = dv.x + dv.y;
            }

            // ---- sequential c updates (short chain) ----
            const float llik0 = c;
            const float err0  = stgt[p0] - dot[0];
            c = __fadd_rn(c, __fadd_rn(__fmul_rn(-0.5f, __fmul_rn(err0, err0)),
                                       LOGNORM));
            const float llik1 = c;
            const float err1  = stgt[p0 + 1] - dot[1];
            c = __fadd_rn(c, __fadd_rn(__fmul_rn(-0.5f, __fmul_rn(err1, err1)),
                                       LOGNORM));

            // ---- two independent softmax partials, chains interleaved ----
            const float m0 = warp_max_nonpos(llik0);
            const float m1 = warp_max_nonpos(llik1);
            const float e0 = mufu_exp(llik0 - m0);   // leader -> exactly 1
            const float e1 = mufu_exp(llik1 - m1);

            float S0 = e0, V0 = e0 * dot[0];
            float S1 = e1, V1 = e1 * dot[1];
            #pragma unroll
            for (int off = 16; off > 0; off >>= 1) {
                S0 += __shfl_xor_sync(0xffffffffu, S0, off);
                V0 += __shfl_xor_sync(0xffffffffu, V0, off);
                S1 += __shfl_xor_sync(0xffffffffu, S1, off);
                V1 += __shfl_xor_sync(0xffffffffu, V1, off);
            }

            if (lane == 0) {
                mypart[(size_t)p0 * NPART]       = make_float4(m0, S0, V0, 0.0f);
                mypart[(size_t)(p0 + 1) * NPART] = make_float4(m1, S1, V1, 0.0f);
            }
        }
        __syncthreads();   // tile consumed; prefetch writes visible
    }
}

// ------------------------------------------------------------------
// Combine: one warp per (b,p); LSE-merge its 128 per-warp partials.
// ------------------------------------------------------------------
__global__ void __launch_bounds__(256)
mmse_combine(float* __restrict__ out)
{
    const int warp = threadIdx.x >> 5;
    const int lane = threadIdx.x & 31;
    const int idx  = blockIdx.x * 8 + warp;    // b*NP + p
    const float4* pp = g_part + (size_t)idx * NPART + lane * 4;

    float4 l0 = pp[0], l1 = pp[1], l2 = pp[2], l3 = pp[3];

    // all m's are <= 0 -> u32-min trick valid
    float m = fmaxf(fmaxf(l0.x, l1.x), fmaxf(l2.x, l3.x));
    m = warp_max_nonpos(m);

    float e0 = mufu_exp(l0.x - m);
    float e1 = mufu_exp(l1.x - m);
    float e2 = mufu_exp(l2.x - m);
    float e3 = mufu_exp(l3.x - m);
    float S = fmaf(e0, l0.y, fmaf(e1, l1.y, fmaf(e2, l2.y, e3 * l3.y)));
    float V = fmaf(e0, l0.z, fmaf(e1, l1.z, fmaf(e2, l2.z, e3 * l3.z)));
    #pragma unroll
    for (int off = 16; off > 0; off >>= 1) {
        S += __shfl_xor_sync(0xffffffffu, S, off);
        V += __shfl_xor_sync(0xffffffffu, V, off);
    }

    if (lane == 0) out[idx] = V / S;
}

// ------------------------------------------------------------------
extern "C" void kernel_launch(void* const* d_in, const int* in_sizes, int n_in,
                              void* d_out, int out_size)
{
    (void)out_size;
    const float* data      = (const float*)d_in[0];
    const float* targets   = (const float*)d_in[1];
    const float* task_pool = (const float*)d_in[2];
    for (int i = 0; i < n_in; ++i) {
        if (in_sizes[i] == NB * NP * ND)      data      = (const float*)d_in[i];
        else if (in_sizes[i] == NB * NP)      targets   = (const float*)d_in[i];
        else if (in_sizes[i] == NT * ND)      task_pool = (const float*)d_in[i];
    }
    float* out = (float*)d_out;   // (B, P)

    dim3 grid(NCHUNK, NB);
    mmse_main<<<grid, 256>>>(data, targets, task_pool);
    mmse_combine<<<(NB * NP) / 8, 256>>>(out);
}

// round 10
// speedup vs baseline: 3.0165x; 1.2714x over previous
#include <cuda_runtime.h>

#define NB 32
#define NP 256
#define ND 64
#define NT 4096
#define TCHUNK 512   // tasks per CTA (2 per thread)
#define NCHUNK 8     // NT / TCHUNK
#define NWARP 8      // warps per CTA
#define NPART (NCHUNK * NWARP)   // 64 per-warp partials per (b,p)
#define PTILE 16     // p rows staged per smem tile

#define LOG2E (1.4426950408889634f)

typedef unsigned long long u64;

// Per-warp partials: (warp max m, sum exp S, sum exp*pred V, pad)
// NOTE: log_norm constant dropped everywhere — it is a uniform per-p shift
// that cancels in the per-p softmax and in the LSE merge. c stays <= 0.
__device__ float4 g_part[NB * NP * NPART];

// ---------- packed f32x2 helpers ----------
__device__ __forceinline__ u64 fma2(u64 a, u64 b, u64 acc) {
    u64 r;
    asm("fma.rn.f32x2 %0, %1, %2, %3;" : "=l"(r) : "l"(a), "l"(b), "l"(acc));
    return r;
}
__device__ __forceinline__ u64 add2(u64 a, u64 b) {
    u64 r;
    asm("add.rn.f32x2 %0, %1, %2;" : "=l"(r) : "l"(a), "l"(b));
    return r;
}
__device__ __forceinline__ float2 u2f(u64 a) {
    float2 r;
    asm("mov.b64 {%0, %1}, %2;" : "=f"(r.x), "=f"(r.y) : "l"(a));
    return r;
}

// Warp float-max for values <= 0 in ONE instruction: non-positive floats
// (+0.0 -> 0x00000000) order inversely to their u32 bit patterns, so
// float-max == u32-min over raw bits (redux.sync int ops: sm_80+).
__device__ __forceinline__ float warp_max_nonpos(float x) {
    return __uint_as_float(__reduce_min_sync(0xffffffffu, __float_as_uint(x)));
}

// exp via MUFU: arg <= 0; leader always evaluates ex2(0)=1 exactly.
__device__ __forceinline__ float mufu_exp(float x) {
    float r;
    asm("ex2.approx.f32 %0, %1;" : "=f"(r) : "f"(x * LOG2E));
    return r;
}

// ------------------------------------------------------------------
// CTA = (t-chunk, b). TWO tasks per thread (t and t+256): every smem
// row load feeds two dots, every warp reduction covers 64 tasks —
// halving LDS/SHFL/REDUX per unit work vs one-task-per-thread.
// ------------------------------------------------------------------
__global__ void __launch_bounds__(256, 1)
mmse_main(const float* __restrict__ data,
          const float* __restrict__ targets,
          const float* __restrict__ task_pool)
{
    const int chunk = blockIdx.x;
    const int b     = blockIdx.y;
    const int tid   = threadIdx.x;
    const int lane  = tid & 31;
    const int warp  = tid >> 5;
    const int tA    = chunk * TCHUNK + tid;        // task A
    const int tB    = tA + 256;                    // task B

    __shared__ float stgt[NP];
    __shared__ float srow[2][PTILE][ND];   // 2 x 4KB row tiles

    // Two W columns as packed f32x2 (128 registers)
    u64 wa[32], wb[32];
    {
        const ulonglong2* wpA = (const ulonglong2*)(task_pool + (size_t)tA * ND);
        const ulonglong2* wpB = (const ulonglong2*)(task_pool + (size_t)tB * ND);
        #pragma unroll
        for (int i = 0; i < 16; ++i) {
            ulonglong2 qa = __ldg(wpA + i);
            ulonglong2 qb = __ldg(wpB + i);
            wa[2 * i] = qa.x; wa[2 * i + 1] = qa.y;
            wb[2 * i] = qb.x; wb[2 * i + 1] = qb.y;
        }
    }
    stgt[tid] = targets[b * NP + tid];

    const float4* dbase4 = (const float4*)(data + (size_t)b * NP * ND);
    ((float4*)srow[0])[tid] = __ldg(dbase4 + tid);   // preload tile 0
    __syncthreads();

    float4* mypart = g_part + ((size_t)b * NP * NCHUNK + chunk) * NWARP + warp;
    float cA = 0.0f, cB = 0.0f;   // exclusive prefix cumsums (<= 0)

    #pragma unroll 1
    for (int tile = 0; tile < NP / PTILE; ++tile) {
        const int buf = tile & 1;

        if (tile + 1 < NP / PTILE)   // prefetch next tile (~16 p's ahead)
            ((float4*)srow[buf ^ 1])[tid] = __ldg(dbase4 + (tile + 1) * 256 + tid);

        #pragma unroll 1
        for (int pp = 0; pp < PTILE; pp += 2) {
            const int p0 = tile * PTILE + pp;

            // ---- 4 dots: rows {p0, p0+1} x tasks {A, B} ----
            float dA[2], dB[2];
            #pragma unroll
            for (int k = 0; k < 2; ++k) {
                const ulonglong2* row = (const ulonglong2*)srow[buf][pp + k];
                u64 a0 = 0ull, a1 = 0ull, b0 = 0ull, b1 = 0ull;
                #pragma unroll
                for (int i = 0; i < 16; i += 2) {
                    ulonglong2 x = row[i];
                    ulonglong2 y = row[i + 1];
                    a0 = fma2(x.x, wa[2 * i],     a0);
                    a1 = fma2(x.y, wa[2 * i + 1], a1);
                    b0 = fma2(x.x, wb[2 * i],     b0);
                    b1 = fma2(x.y, wb[2 * i + 1], b1);
                    a0 = fma2(y.x, wa[2 * i + 2], a0);
                    a1 = fma2(y.y, wa[2 * i + 3], a1);
                    b0 = fma2(y.x, wb[2 * i + 2], b0);
                    b1 = fma2(y.y, wb[2 * i + 3], b1);
                }
                a0 = add2(a0, a1);
                b0 = add2(b0, b1);
                const float2 va = u2f(a0);
                const float2 vb = u2f(b0);
                dA[k] = va.x + va.y;
                dB[k] = vb.x + vb.y;
            }

            // ---- p0: logits, scores, partial ----
            const float tg0 = stgt[p0];
            const float lA0 = cA, lB0 = cB;
            {
                const float eA = tg0 - dA[0];
                const float eB = tg0 - dB[0];
                cA = fmaf(-0.5f * eA, eA, cA);
                cB = fmaf(-0.5f * eB, eB, cB);
            }
            // ---- p1 scores (dots already available) ----
            const float tg1 = stgt[p0 + 1];
            const float lA1 = cA, lB1 = cB;
            {
                const float eA = tg1 - dA[1];
                const float eB = tg1 - dB[1];
                cA = fmaf(-0.5f * eA, eA, cA);
                cB = fmaf(-0.5f * eB, eB, cB);
            }

            // ---- two softmax partials (64 tasks each), chains interleaved ----
            const float m0 = warp_max_nonpos(fmaxf(lA0, lB0));
            const float m1 = warp_max_nonpos(fmaxf(lA1, lB1));
            const float eA0 = mufu_exp(lA0 - m0);
            const float eB0 = mufu_exp(lB0 - m0);
            const float eA1 = mufu_exp(lA1 - m1);
            const float eB1 = mufu_exp(lB1 - m1);

            float S0 = eA0 + eB0;
            float V0 = fmaf(eA0, dA[0], eB0 * dB[0]);
            float S1 = eA1 + eB1;
            float V1 = fmaf(eA1, dA[1], eB1 * dB[1]);
            #pragma unroll
            for (int off = 16; off > 0; off >>= 1) {
                S0 += __shfl_xor_sync(0xffffffffu, S0, off);
                V0 += __shfl_xor_sync(0xffffffffu, V0, off);
                S1 += __shfl_xor_sync(0xffffffffu, S1, off);
                V1 += __shfl_xor_sync(0xffffffffu, V1, off);
            }

            if (lane == 0) {
                mypart[(size_t)p0 * NPART]       = make_float4(m0, S0, V0, 0.0f);
                mypart[(size_t)(p0 + 1) * NPART] = make_float4(m1, S1, V1, 0.0f);
            }
        }
        __syncthreads();   // tile consumed; prefetch writes visible
    }
}

// ------------------------------------------------------------------
// Combine: one warp per (b,p); LSE-merge its 64 per-warp partials.
// ------------------------------------------------------------------
__global__ void __launch_bounds__(256)
mmse_combine(float* __restrict__ out)
{
    const int warp = threadIdx.x >> 5;
    const int lane = threadIdx.x & 31;
    const int idx  = blockIdx.x * 8 + warp;    // b*NP + p
    const float4* pp = g_part + (size_t)idx * NPART + lane * 2;

    float4 l0 = pp[0], l1 = pp[1];

    // all m's <= 0 -> u32-min trick valid
    float m = warp_max_nonpos(fmaxf(l0.x, l1.x));

    float e0 = mufu_exp(l0.x - m);
    float e1 = mufu_exp(l1.x - m);
    float S = fmaf(e0, l0.y, e1 * l1.y);
    float V = fmaf(e0, l0.z, e1 * l1.z);
    #pragma unroll
    for (int off = 16; off > 0; off >>= 1) {
        S += __shfl_xor_sync(0xffffffffu, S, off);
        V += __shfl_xor_sync(0xffffffffu, V, off);
    }

    if (lane == 0) out[idx] = V / S;
}

// ------------------------------------------------------------------
extern "C" void kernel_launch(void* const* d_in, const int* in_sizes, int n_in,
                              void* d_out, int out_size)
{
    (void)out_size;
    const float* data      = (const float*)d_in[0];
    const float* targets   = (const float*)d_in[1];
    const float* task_pool = (const float*)d_in[2];
    for (int i = 0; i < n_in; ++i) {
        if (in_sizes[i] == NB * NP * ND)      data      = (const float*)d_in[i];
        else if (in_sizes[i] == NB * NP)      targets   = (const float*)d_in[i];
        else if (in_sizes[i] == NT * ND)      task_pool = (const float*)d_in[i];
    }
    float* out = (float*)d_out;   // (B, P)

    dim3 grid(NCHUNK, NB);
    mmse_main<<<grid, 256>>>(data, targets, task_pool);
    mmse_combine<<<(NB * NP) / 8, 256>>>(out);
}